// round 4
// baseline (speedup 1.0000x reference)
#include <cuda_runtime.h>
#include <cuda_bf16.h>
#include <cstdint>

// Embedding gather via bulk-async (TMA) DMA pipeline.
// out[t, :] = weight[token_ids[t], :]   rows are 4 KB (1024 fp32), 4KB-aligned.
//
// Each CTA (1 warp) owns TPC consecutive tokens. Pipeline:
//   gmem row --cp.async.bulk--> smem stage --cp.async.bulk--> gmem out
// STAGES=8 ring, AHEAD=6 loads in flight, store groups bounded by wait_group.read.

static constexpr int ROW_BYTES = 4096;
static constexpr int STAGES    = 8;
static constexpr int MARGIN    = 2;              // outstanding store groups allowed at reuse
static constexpr int AHEAD     = STAGES - MARGIN; // 6 loads in flight
static constexpr int TPC       = 16;             // tokens per CTA

__device__ __forceinline__ uint32_t smem_u32(const void* p) {
    return (uint32_t)__cvta_generic_to_shared(p);
}

__device__ __forceinline__ void mbar_init(uint32_t mbar, uint32_t count) {
    asm volatile("mbarrier.init.shared::cta.b64 [%0], %1;" :: "r"(mbar), "r"(count) : "memory");
}

__device__ __forceinline__ void mbar_expect_tx(uint32_t mbar, uint32_t bytes) {
    asm volatile("mbarrier.arrive.expect_tx.shared::cta.b64 _, [%0], %1;"
                 :: "r"(mbar), "r"(bytes) : "memory");
}

__device__ __forceinline__ void mbar_wait_parity(uint32_t mbar, uint32_t parity) {
    asm volatile(
        "{\n\t"
        ".reg .pred P;\n\t"
        "WAIT_%=:\n\t"
        "mbarrier.try_wait.parity.acquire.cta.shared::cta.b64 P, [%0], %1, 0x989680;\n\t"
        "@P bra.uni DONE_%=;\n\t"
        "bra.uni WAIT_%=;\n\t"
        "DONE_%=:\n\t"
        "}"
        :: "r"(mbar), "r"(parity) : "memory");
}

__device__ __forceinline__ void bulk_load_g2s(uint32_t smem_dst, const void* gmem_src,
                                              uint32_t bytes, uint32_t mbar) {
    asm volatile(
        "cp.async.bulk.shared::cta.global.mbarrier::complete_tx::bytes [%0], [%1], %2, [%3];"
        :: "r"(smem_dst), "l"(gmem_src), "r"(bytes), "r"(mbar) : "memory");
}

__device__ __forceinline__ void bulk_store_s2g(void* gmem_dst, uint32_t smem_src,
                                               uint32_t bytes) {
    asm volatile(
        "cp.async.bulk.global.shared::cta.bulk_group [%0], [%1], %2;"
        :: "l"(gmem_dst), "r"(smem_src), "r"(bytes) : "memory");
}

__device__ __forceinline__ void bulk_commit() {
    asm volatile("cp.async.bulk.commit_group;" ::: "memory");
}

template <int N>
__device__ __forceinline__ void bulk_wait_read() {
    asm volatile("cp.async.bulk.wait_group.read %0;" :: "n"(N) : "memory");
}

template <int N>
__device__ __forceinline__ void bulk_wait() {
    asm volatile("cp.async.bulk.wait_group %0;" :: "n"(N) : "memory");
}

__global__ __launch_bounds__(32)
void embedding_tma_kernel(const int* __restrict__ token_ids,
                          const char* __restrict__ weight,
                          char* __restrict__ out,
                          int n_tokens) {
    __shared__ __align__(1024) unsigned char buf[STAGES * ROW_BYTES];
    __shared__ __align__(8)    uint64_t      mbar[STAGES];
    __shared__                 int           sids[TPC];

    const int lane = threadIdx.x;
    const int t0   = blockIdx.x * TPC;
    const int n    = (t0 + TPC <= n_tokens) ? TPC : (n_tokens - t0);
    if (n <= 0) return;

    // Prefetch this CTA's token ids into smem (cooperative, independent loads).
    if (lane < n) sids[lane] = __ldg(token_ids + t0 + lane);
    if (lane == 0) {
#pragma unroll
        for (int s = 0; s < STAGES; ++s) mbar_init(smem_u32(&mbar[s]), 1);
    }
    __syncwarp();

    if (lane != 0) return;   // single-thread DMA driver; engines do the work

    const uint32_t buf_base  = smem_u32(buf);
    const uint32_t mbar_base = smem_u32(mbar);

    // Prologue: fill the pipeline with AHEAD loads.
    const int np = (AHEAD < n) ? AHEAD : n;
#pragma unroll
    for (int i = 0; i < np; ++i) {
        const int s = i % STAGES;
        mbar_expect_tx(mbar_base + 8u * s, ROW_BYTES);
        bulk_load_g2s(buf_base + (uint32_t)s * ROW_BYTES,
                      weight + (size_t)sids[i] * ROW_BYTES,
                      ROW_BYTES, mbar_base + 8u * s);
    }

    // Steady state.
    for (int i = 0; i < n; ++i) {
        const int s = i % STAGES;
        mbar_wait_parity(mbar_base + 8u * s, (uint32_t)((i / STAGES) & 1));

        bulk_store_s2g(out + (size_t)(t0 + i) * ROW_BYTES,
                       buf_base + (uint32_t)s * ROW_BYTES, ROW_BYTES);
        bulk_commit();

        const int j = i + AHEAD;
        if (j < n) {
            // Stage (j % STAGES)'s previous store was committed MARGIN groups ago;
            // wait until smem reads of all but the MARGIN newest groups are done.
            bulk_wait_read<MARGIN>();
            const int s2 = j % STAGES;
            mbar_expect_tx(mbar_base + 8u * s2, ROW_BYTES);
            bulk_load_g2s(buf_base + (uint32_t)s2 * ROW_BYTES,
                          weight + (size_t)sids[j] * ROW_BYTES,
                          ROW_BYTES, mbar_base + 8u * s2);
        }
    }

    // Drain all outstanding store groups before CTA exit.
    bulk_wait<0>();
}

extern "C" void kernel_launch(void* const* d_in, const int* in_sizes, int n_in,
                              void* d_out, int out_size) {
    const int* token_ids = (const int*)d_in[0];
    const char* weight   = (const char*)d_in[1];
    char* out            = (char*)d_out;

    int n_tokens = in_sizes[0];                 // 8192
    int n_ctas   = (n_tokens + TPC - 1) / TPC;  // 512

    embedding_tma_kernel<<<n_ctas, 32>>>(token_ids, weight, out, n_tokens);
}